// round 5
// baseline (speedup 1.0000x reference)
#include <cuda_runtime.h>
#include <cuda_fp16.h>
#include <cstdint>

// ThresholdDecision: out[b] = 1 iff exists t in [1, L-CP-1] with
// x[b, t..t+CP-1, 2] > 0.5 (CP=4), else 0. From the reference's
// diffs = c[:, CP:L-1] - c[:, :L-CP-1]; any(diffs == CP).
//
// ROUND-4 KEY FIX: the output buffer dtype follows metadata.txt, and three
// rounds of rel_err == exactly 1.0 (invariant to writing int 1 vs int 3) are
// only explained by d_out being FLOAT32: int bit patterns 1 and 3 read back
// as denormals ~ 0.0, giving ||0 - 1||/||1|| = 1.0 every time. Write floats.
//
// Failure-mode discrimination if this still fails:
//   rel_err ~ 2.0  -> kernel ran, found no >0.5 runs (input-side issue)
//   rel_err ~ 1e9  -> output really is int32 (float 1.0f = 1065353216)
//   rel_err = 1.0  -> writes not landing at all (launch/output-path issue)

#define NTHREADS 256
#define CP 4

__global__ void __launch_bounds__(NTHREADS)
threshold_decision_kernel(const void* __restrict__ xraw,
                          float* __restrict__ out,
                          int L)
{
    const int row = blockIdx.x;
    const int tid = threadIdx.x;

    // dtype probe: fp16 iff all of the first 64 words have both 16-bit halves
    // < 0x3C00 (every half < 1.0 as fp16). Genuine uniform fp32 data fails
    // this with overwhelming probability; deterministic function of input.
    const uint32_t w = ((const uint32_t*)xraw)[tid & 63];
    const int looks_fp16 = ((w & 0xFFFFu) < 0x3C00u) && ((w >> 16) < 0x3C00u);
    const int is_fp16 = __syncthreads_and(looks_fp16);

    const int t_max = L - CP - 1;   // last valid window start (t+3 <= L-2)
    int any = 0;

    if (is_fp16) {
        const __half* __restrict__ xr =
            (const __half*)xraw + (size_t)row * (size_t)L * 3u;
        for (int base = 1; base <= t_max; base += NTHREADS) {
            const int t = base + tid;
            int pred = 0;
            if (t <= t_max) {
                const float v0 = __half2float(xr[(size_t)(t + 0) * 3 + 2]);
                const float v1 = __half2float(xr[(size_t)(t + 1) * 3 + 2]);
                const float v2 = __half2float(xr[(size_t)(t + 2) * 3 + 2]);
                const float v3 = __half2float(xr[(size_t)(t + 3) * 3 + 2]);
                pred = (v0 > 0.5f) && (v1 > 0.5f) &&
                       (v2 > 0.5f) && (v3 > 0.5f);
            }
            if (__syncthreads_or(pred)) { any = 1; break; }
        }
    } else {
        const float* __restrict__ xr =
            (const float*)xraw + (size_t)row * (size_t)L * 3u;
        for (int base = 1; base <= t_max; base += NTHREADS) {
            const int t = base + tid;
            int pred = 0;
            if (t <= t_max) {
                const float v0 = xr[(size_t)(t + 0) * 3 + 2];
                const float v1 = xr[(size_t)(t + 1) * 3 + 2];
                const float v2 = xr[(size_t)(t + 2) * 3 + 2];
                const float v3 = xr[(size_t)(t + 3) * 3 + 2];
                pred = (v0 > 0.5f) && (v1 > 0.5f) &&
                       (v2 > 0.5f) && (v3 > 0.5f);
            }
            if (__syncthreads_or(pred)) { any = 1; break; }
        }
    }

    // FLOAT output. Sentinel 3.0f on not-found (cannot occur on the fixed
    // dataset; pure failure-mode discriminator).
    if (tid == 0) out[row] = any ? 1.0f : 3.0f;
}

extern "C" void kernel_launch(void* const* d_in, const int* in_sizes, int n_in,
                              void* d_out, int out_size)
{
    const int B = out_size;   // one flag per row

    // Select the input whose element count is divisible by B*3.
    const void* x = d_in[0];
    long long total = in_sizes[0];
    for (int i = 0; i < n_in; ++i) {
        long long s = in_sizes[i];
        if (s >= (long long)B * 3 && s % ((long long)B * 3) == 0) {
            x = d_in[i];
            total = s;
            break;
        }
    }
    const int L = (int)(total / ((long long)B * 3));

    threshold_decision_kernel<<<B, NTHREADS>>>(x, (float*)d_out, L);
}

// round 6
// speedup vs baseline: 1.2870x; 1.2870x over previous
#include <cuda_runtime.h>
#include <cstdint>

// ThresholdDecision: out[b] = 1.0f iff exists t in [1, L-CP-1] with
// x[b, t..t+CP-1, 2] > 0.5 (CP=4), else 0.0f. Output dtype is FLOAT32
// (confirmed R5). Input is fp32 [B, L, 3] interleaved.
//
// R5 -> R6: block-per-row (1.05M threads, 3.5 waves) was wave/latency-bound.
// Now ONE WARP PER ROW: 4096 warps = 131K threads -> entire grid resident in
// a single wave. Per chunk a warp covers 256 positions:
//   8 coalesced loads/thread (stride 12B, 384B/warp/ballot), MLP=8
//   -> one DRAM round trip, then 8 __ballot_sync + cheap 35-bit run-of-4
//   shift-AND with a 3-bit carry across words/chunks. No block barriers.
// P(no run of 4 in 256 uniform bits) ~ e^-8 -> ~1 row in 4096 takes chunk 2.

#define WARPS_PER_BLOCK 8
#define NTHREADS (WARPS_PER_BLOCK * 32)
#define CP 4
#define BALLOTS_PER_CHUNK 8
#define CHUNK (BALLOTS_PER_CHUNK * 32)   // 256 positions per warp chunk

__global__ void __launch_bounds__(NTHREADS)
threshold_decision_kernel(const float* __restrict__ x,
                          float* __restrict__ out,
                          int L, int B)
{
    const int lane = threadIdx.x & 31;
    const int warp = threadIdx.x >> 5;
    const int row  = blockIdx.x * WARPS_PER_BLOCK + warp;
    if (row >= B) return;

    const float* __restrict__ xr = x + (size_t)row * (size_t)L * 3u;

    unsigned long long carry = 0ull;   // last 3 position-bits of the stream
    int found = 0;

    for (int base = 0; base < L && !found; base += CHUNK) {
        // Phase 1: fire all loads (independent -> MLP = 8, one round trip).
        float v[BALLOTS_PER_CHUNK];
        #pragma unroll
        for (int j = 0; j < BALLOTS_PER_CHUNK; ++j) {
            const int p = base + j * 32 + lane;
            v[j] = (p < L) ? __ldg(&xr[(size_t)p * 3 + 2]) : 0.0f;
        }

        // Phase 2: ballots + run-of-4 detection.
        #pragma unroll
        for (int j = 0; j < BALLOTS_PER_CHUNK; ++j) {
            const int p = base + j * 32 + lane;
            // positions 0 and L-1 never participate (window t>=1, t+3<=L-2)
            const int pred = (v[j] > 0.5f) & (p >= 1) & (p <= L - 2);
            const unsigned int w = __ballot_sync(0xffffffffu, pred);
            // 35-bit container: 3 carry bits + 32 new bits; detects every
            // run of 4 ending inside this word or spanning the boundary.
            const unsigned long long t = ((unsigned long long)w << 3) | carry;
            const unsigned long long r = t & (t >> 1) & (t >> 2) & (t >> 3);
            found |= (r != 0ull);
            carry = (unsigned long long)(w >> 29);
        }
    }

    if (lane == 0) out[row] = found ? 1.0f : 0.0f;
}

extern "C" void kernel_launch(void* const* d_in, const int* in_sizes, int n_in,
                              void* d_out, int out_size)
{
    const int B = out_size;   // one flag per row

    // Select the input whose element count is divisible by B*3.
    const float* x = (const float*)d_in[0];
    long long total = in_sizes[0];
    for (int i = 0; i < n_in; ++i) {
        long long s = in_sizes[i];
        if (s >= (long long)B * 3 && s % ((long long)B * 3) == 0) {
            x = (const float*)d_in[i];
            total = s;
            break;
        }
    }
    const int L = (int)(total / ((long long)B * 3));

    const int grid = (B + WARPS_PER_BLOCK - 1) / WARPS_PER_BLOCK;
    threshold_decision_kernel<<<grid, NTHREADS>>>(x, (float*)d_out, L, B);
}

// round 8
// speedup vs baseline: 1.2930x; 1.0047x over previous
#include <cuda_runtime.h>
#include <cstdint>

// ThresholdDecision: out[b] = 1.0f iff exists t in [1, L-CP-1] with
// x[b, t..t+CP-1, 2] > 0.5 (CP=4), else 0.0f. fp32 in, fp32 out.
//
// R6 -> R7: duration == traffic / ~2.3 TB/s (latency x outstanding regime,
// L1tex-queue capped). So cut traffic: geometric chunk schedule 64 -> 192 ->
// 1024... Expected first 4-run at position ~30, so 86.5% of rows finish on
// the 64-position chunk. Expected traffic ~4.5 MB vs 12.6 MB flat-256.
// Tail bounded to <= 3 round trips for all but ~e^-8 of rows.

#define WARPS_PER_BLOCK 8
#define NTHREADS (WARPS_PER_BLOCK * 32)

// Scan W ballot-words (W*32 positions) starting at position `base`.
// carry holds the top 3 bits of the previous word's stream. Returns
// warp-uniform found flag.
template <int W>
__device__ __forceinline__ int scan_words(const float* __restrict__ xr,
                                          int base, int L, int lane,
                                          unsigned int& carry)
{
    float v[W];
    #pragma unroll
    for (int j = 0; j < W; ++j) {
        const int p = base + j * 32 + lane;
        v[j] = (p < L) ? __ldg(&xr[(size_t)p * 3 + 2]) : 0.0f;
    }

    int found = 0;
    #pragma unroll
    for (int j = 0; j < W; ++j) {
        const int p = base + j * 32 + lane;
        // positions 0 and L-1 excluded (window t >= 1, t+3 <= L-2)
        const int pred = (v[j] > 0.5f) & (p >= 1) & (p <= L - 2);
        const unsigned int w = __ballot_sync(0xffffffffu, pred);
        const unsigned long long t = ((unsigned long long)w << 3) | carry;
        const unsigned long long r = t & (t >> 1) & (t >> 2) & (t >> 3);
        found |= (r != 0ull);
        carry = w >> 29;
    }
    return found;
}

__global__ void __launch_bounds__(NTHREADS)
threshold_decision_kernel(const float* __restrict__ x,
                          float* __restrict__ out,
                          int L, int B)
{
    const int lane = threadIdx.x & 31;
    const int warp = threadIdx.x >> 5;
    const int row  = blockIdx.x * WARPS_PER_BLOCK + warp;
    if (row >= B) return;

    const float* __restrict__ xr = x + (size_t)row * (size_t)L * 3u;

    unsigned int carry = 0u;
    // Phase 1: 64 positions (2 words). ~86.5% of rows stop here.
    int found = scan_words<2>(xr, 0, L, lane, carry);

    // Phase 2: next 192 positions (6 words). Cumulative 256 -> miss P ~ e^-8.
    if (!found && L > 64)
        found = scan_words<6>(xr, 64, L, lane, carry);

    // Phase 3+: 1024-position chunks until done (exhaustive fallback).
    for (int base = 256; !found && base < L; base += 1024)
        found = scan_words<32>(xr, base, L, lane, carry);

    if (lane == 0) out[row] = found ? 1.0f : 0.0f;
}

extern "C" void kernel_launch(void* const* d_in, const int* in_sizes, int n_in,
                              void* d_out, int out_size)
{
    const int B = out_size;   // one flag per row

    // Select the input whose element count is divisible by B*3.
    const float* x = (const float*)d_in[0];
    long long total = in_sizes[0];
    for (int i = 0; i < n_in; ++i) {
        long long s = in_sizes[i];
        if (s >= (long long)B * 3 && s % ((long long)B * 3) == 0) {
            x = (const float*)d_in[i];
            total = s;
            break;
        }
    }
    const int L = (int)(total / ((long long)B * 3));

    const int grid = (B + WARPS_PER_BLOCK - 1) / WARPS_PER_BLOCK;
    threshold_decision_kernel<<<grid, NTHREADS>>>(x, (float*)d_out, L, B);
}

// round 12
// speedup vs baseline: 1.3430x; 1.0386x over previous
#include <cuda_runtime.h>
#include <cstdint>

// ThresholdDecision: out[b] = 1.0f iff exists t in [1, L-CP-1] with
// x[b, t..t+CP-1, 2] > 0.5 (CP=4), else 0.0f. fp32 in, fp32 out.
//
// R8: run-start rate is 1/32 per position (pattern 0,1111 = 2^-5), so
// P(row needs > n positions) ~ e^(-n/32). Schedule 64 -> +288 (cum 352)
// leaves e^-11 * 4096 ~ 0.07 rows for the fallback -> typical run has NO
// third round trip; critical path = 2 dependent DRAM trips. Expected
// traffic ~4.9 MB (vs 201 MB full scan). Fallback 1024-chunks for
// determinism on adversarial data.

#define WARPS_PER_BLOCK 8
#define NTHREADS (WARPS_PER_BLOCK * 32)

// Scan W ballot-words (W*32 positions) starting at `base`. carry holds the
// top 3 bits of the previous word's bit-stream. Returns warp-uniform flag.
template <int W>
__device__ __forceinline__ int scan_words(const float* __restrict__ xr,
                                          int base, int L, int lane,
                                          unsigned int& carry)
{
    float v[W];
    #pragma unroll
    for (int j = 0; j < W; ++j) {
        const int p = base + j * 32 + lane;
        v[j] = (p < L) ? __ldg(&xr[(size_t)p * 3 + 2]) : 0.0f;
    }

    int found = 0;
    #pragma unroll
    for (int j = 0; j < W; ++j) {
        const int p = base + j * 32 + lane;
        // positions 0 and L-1 excluded (window t >= 1, t+3 <= L-2)
        const int pred = (v[j] > 0.5f) & (p >= 1) & (p <= L - 2);
        const unsigned int w = __ballot_sync(0xffffffffu, pred);
        const unsigned long long t = ((unsigned long long)w << 3) | carry;
        const unsigned long long r = t & (t >> 1) & (t >> 2) & (t >> 3);
        found |= (r != 0ull);
        carry = w >> 29;
    }
    return found;
}

__global__ void __launch_bounds__(NTHREADS)
threshold_decision_kernel(const float* __restrict__ x,
                          float* __restrict__ out,
                          int L, int B)
{
    const int lane = threadIdx.x & 31;
    const int warp = threadIdx.x >> 5;
    const int row  = blockIdx.x * WARPS_PER_BLOCK + warp;
    if (row >= B) return;

    const float* __restrict__ xr = x + (size_t)row * (size_t)L * 3u;

    unsigned int carry = 0u;
    // Phase 1: 64 positions (2 words). ~86.5% of rows stop here.
    int found = scan_words<2>(xr, 0, L, lane, carry);

    // Phase 2: +288 positions (9 words), cumulative 352.
    // P(still missing) ~ e^-11 -> ~0.07 rows chip-wide hit the fallback.
    if (!found && L > 64)
        found = scan_words<9>(xr, 64, L, lane, carry);

    // Fallback: 1024-position chunks (exhaustive, determinism guarantee).
    for (int base = 352; !found && base < L; base += 1024)
        found = scan_words<32>(xr, base, L, lane, carry);

    if (lane == 0) out[row] = found ? 1.0f : 0.0f;
}

extern "C" void kernel_launch(void* const* d_in, const int* in_sizes, int n_in,
                              void* d_out, int out_size)
{
    const int B = out_size;   // one flag per row

    // Select the input whose element count is divisible by B*3.
    const float* x = (const float*)d_in[0];
    long long total = in_sizes[0];
    for (int i = 0; i < n_in; ++i) {
        long long s = in_sizes[i];
        if (s >= (long long)B * 3 && s % ((long long)B * 3) == 0) {
            x = (const float*)d_in[i];
            total = s;
            break;
        }
    }
    const int L = (int)(total / ((long long)B * 3));

    const int grid = (B + WARPS_PER_BLOCK - 1) / WARPS_PER_BLOCK;
    threshold_decision_kernel<<<grid, NTHREADS>>>(x, (float*)d_out, L, B);
}